// round 1
// baseline (speedup 1.0000x reference)
#include <cuda_runtime.h>
#include <cuda_bf16.h>
#include <cstdint>

// YOLO-style detect head:
//  out[b, hw, o] = decode( sigmoid( sum_c feat[b,c,hw] * W[o,c] + bias[o] ) )
// per level; levels concatenated along position axis (offsets 0, 6400, 8000).

#define OC 85
#define KC 16          // K-chunk staged in shared
#define TPB 128        // threads per block = positions per block

// Shared: first KC*88 floats alias the W-chunk (row stride 88, float4-aligned);
// epilogue reuses the whole buffer as S[pos][89] (odd stride -> conflict-free).
#define WROW 88
#define SROW 89

template <int C, int NY, int NX, int LEVEL>
__global__ __launch_bounds__(TPB)
void detect_level_kernel(const float* __restrict__ feat,
                         const float* __restrict__ Wm,
                         const float* __restrict__ bias,
                         float* __restrict__ out,
                         int levelOffset)
{
    __shared__ float S[TPB * SROW];   // 128*89*4 = 45568 B
    float* Ws = S;                    // [KC][WROW] chunk of W, transposed

    const int tid = threadIdx.x;
    const int b   = blockIdx.y;
    const int hw0 = blockIdx.x * TPB;
    const int hw  = hw0 + tid;
    const int NHW = NY * NX;
    const bool valid = (hw < NHW);
    const int hwc = valid ? hw : (NHW - 1);

    float acc[OC];
#pragma unroll
    for (int o = 0; o < OC; o++) acc[o] = __ldg(&bias[o]);

    const float* fbase = feat + ((size_t)b * C) * NHW + hwc;

    for (int c0 = 0; c0 < C; c0 += KC) {
        __syncthreads();
        // stage W[o, c0..c0+KC) transposed into Ws[kk][o]
        for (int i = tid; i < OC * KC; i += TPB) {
            int kk = i / OC;
            int o  = i - kk * OC;
            Ws[kk * WROW + o] = __ldg(&Wm[o * C + c0 + kk]);
        }
        __syncthreads();

        // prefetch KC feature values (coalesced: consecutive hw across threads)
        float v[KC];
#pragma unroll
        for (int kk = 0; kk < KC; kk++)
            v[kk] = fbase[(size_t)(c0 + kk) * NHW];

#pragma unroll
        for (int kk = 0; kk < KC; kk++) {
            const float4* w4 = reinterpret_cast<const float4*>(Ws + kk * WROW);
            const float vv = v[kk];
#pragma unroll
            for (int j = 0; j < 21; j++) {        // 84 channels via float4 broadcast LDS
                float4 w = w4[j];
                acc[4 * j + 0] = fmaf(vv, w.x, acc[4 * j + 0]);
                acc[4 * j + 1] = fmaf(vv, w.y, acc[4 * j + 1]);
                acc[4 * j + 2] = fmaf(vv, w.z, acc[4 * j + 2]);
                acc[4 * j + 3] = fmaf(vv, w.w, acc[4 * j + 3]);
            }
            acc[84] = fmaf(vv, Ws[kk * WROW + 84], acc[84]);
        }
    }

    // ---- sigmoid + box decode ----
#pragma unroll
    for (int o = 0; o < OC; o++)
        acc[o] = 1.0f / (1.0f + __expf(-acc[o]));

    {
        const float stride = (float)(8 << LEVEL);
        const float power  = (float)(1 << LEVEL);   // 2^level
        const int ix = hwc % NX;
        const int iy = hwc / NX;

        float d0 = acc[0] * 2.0f; d0 = d0 * d0 * power;
        float d1 = acc[1] * 2.0f; d1 = d1 * d1 * power;
        float d2 = acc[2] * 2.0f; d2 = d2 * d2 * power;
        float d3 = acc[3] * 2.0f; d3 = d3 * d3 * power;

        float x1 = ((float)ix + 1.0f - d0) * stride;
        float y1 = ((float)iy + 1.0f - d1) * stride;
        float x2 = ((float)ix + d2) * stride;
        float y2 = ((float)iy + d3) * stride;

        acc[0] = (x1 + x2) * 0.5f;
        acc[1] = (y1 + y2) * 0.5f;
        acc[2] = x2 - x1;
        acc[3] = y2 - y1;
    }

    // ---- coalesced store via shared staging ----
    __syncthreads();
#pragma unroll
    for (int o = 0; o < OC; o++)
        S[tid * SROW + o] = acc[o];
    __syncthreads();

    const int nvalid = min(TPB, NHW - hw0);
    const int total = nvalid * OC;
    float* obase = out + ((size_t)b * 8400 + levelOffset + hw0) * OC;
    for (int i = tid; i < total; i += TPB) {
        int p = i / OC;
        int o = i - p * OC;
        obase[i] = S[p * SROW + o];
    }
}

extern "C" void kernel_launch(void* const* d_in, const int* in_sizes, int n_in,
                              void* d_out, int out_size)
{
    const float* x0 = (const float*)d_in[0];
    const float* x1 = (const float*)d_in[1];
    const float* x2 = (const float*)d_in[2];
    const float* W0 = (const float*)d_in[3];
    const float* b0 = (const float*)d_in[4];
    const float* W1 = (const float*)d_in[5];
    const float* b1 = (const float*)d_in[6];
    const float* W2 = (const float*)d_in[7];
    const float* b2 = (const float*)d_in[8];
    float* out = (float*)d_out;

    const int BS = 16;

    // level 0: 80x80, C=256, stride 8, offset 0
    {
        dim3 grid((80 * 80 + TPB - 1) / TPB, BS);
        detect_level_kernel<256, 80, 80, 0><<<grid, TPB>>>(x0, W0, b0, out, 0);
    }
    // level 1: 40x40, C=512, stride 16, offset 6400
    {
        dim3 grid((40 * 40 + TPB - 1) / TPB, BS);
        detect_level_kernel<512, 40, 40, 1><<<grid, TPB>>>(x1, W1, b1, out, 6400);
    }
    // level 2: 20x20, C=1024, stride 32, offset 8000
    {
        dim3 grid((20 * 20 + TPB - 1) / TPB, BS);
        detect_level_kernel<1024, 20, 20, 2><<<grid, TPB>>>(x2, W2, b2, out, 8000);
    }
}

// round 2
// speedup vs baseline: 2.0990x; 2.0990x over previous
#include <cuda_runtime.h>
#include <cuda_bf16.h>
#include <cstdint>

// Fused YOLO detect head, all 3 levels in one launch.
// GEMM view per level: D[M=NHW, N=85] = X[M, K=C] * W^T, then sigmoid + decode.
// Register tiling: block = 128 positions x 96 outs (85 padded), 256 thr = 32(M) x 8(N),
// thread tile 4x12 -> 48 FMAs per 7 shared loads.

#define TPB 256
#define BM 128          // positions per block
#define NPAD 96         // padded output channels
#define NT 12           // outputs per thread
#define KC 16           // K-chunk
#define SROW 91         // epilogue staging row stride (odd-ish, conflict-light)

// shared: main loop needs KC*NPAD + KC*BM = 1536+2048 = 3584 floats,
// epilogue staging needs 64*SROW = 5824 floats. Union.
#define SMEM_FLOATS 5824

__device__ __forceinline__ float fast_sigmoid(float x) {
    return __fdividef(1.0f, 1.0f + __expf(-x));
}

template <int C, int NY, int NX, int LEVEL>
__device__ __forceinline__
void run_level(const float* __restrict__ feat,
               const float* __restrict__ Wm,
               const float* __restrict__ bias,
               float* __restrict__ out,
               int lvlOff, int mblk, int b, float* smem)
{
    constexpr int NHW = NY * NX;
    float* Ws = smem;              // [KC][NPAD]
    float* Xs = smem + KC * NPAD;  // [KC][BM]

    const int tid = threadIdx.x;
    const int mt = tid & 31;       // lane -> M sub-tile
    const int nt = tid >> 5;       // warp -> N sub-tile
    const int hw0 = mblk * BM;

    float acc[4][NT];
#pragma unroll
    for (int i = 0; i < 4; i++)
#pragma unroll
        for (int j = 0; j < NT; j++) acc[i][j] = 0.0f;

    // bias for this thread's output columns
    float bj[NT];
#pragma unroll
    for (int j = 0; j < NT; j++) {
        int o = nt * NT + j;
        bj[j] = (o < 85) ? __ldg(&bias[o]) : 0.0f;
    }

    const float* fb = feat + (size_t)b * C * NHW;

    for (int c0 = 0; c0 < C; c0 += KC) {
        __syncthreads();
        // ---- stage W chunk transposed: Ws[kk][o] = W[o][c0+kk] ----
        // each thread reads a float4 along K (coalesced-ish), scatters 4 STS (4-way max)
        {
            int idx = tid;
#pragma unroll
            for (int it = 0; it < 2; it++, idx += TPB) {
                if (idx < (KC * NPAD) / 4) {
                    int o  = idx >> 2;
                    int k4 = (idx & 3) * 4;
                    float4 wv = make_float4(0.f, 0.f, 0.f, 0.f);
                    if (o < 85) wv = *(const float4*)&Wm[(size_t)o * C + c0 + k4];
                    Ws[(k4 + 0) * NPAD + o] = wv.x;
                    Ws[(k4 + 1) * NPAD + o] = wv.y;
                    Ws[(k4 + 2) * NPAD + o] = wv.z;
                    Ws[(k4 + 3) * NPAD + o] = wv.w;
                }
            }
        }
        // ---- stage X chunk: Xs[kk][m] = feat[b, c0+kk, hw0+m] (coalesced float4) ----
        {
#pragma unroll
            for (int it = 0; it < 2; it++) {
                int idx = tid + it * TPB;              // < 512
                int kk = idx >> 5;
                int m4 = (idx & 31) * 4;
                const float* src = fb + (size_t)(c0 + kk) * NHW;
                int hwq = hw0 + m4;
                float4 xv;
                if (hwq + 3 < NHW) {
                    xv = *(const float4*)&src[hwq];
                } else {
                    xv.x = src[min(hwq + 0, NHW - 1)];
                    xv.y = src[min(hwq + 1, NHW - 1)];
                    xv.z = src[min(hwq + 2, NHW - 1)];
                    xv.w = src[min(hwq + 3, NHW - 1)];
                }
                *(float4*)&Xs[kk * BM + m4] = xv;
            }
        }
        __syncthreads();

        // ---- 4x12 register-tile FMA ----
#pragma unroll 4
        for (int kk = 0; kk < KC; kk++) {
            float4 xv = *(const float4*)&Xs[kk * BM + mt * 4];
            float4 w0 = *(const float4*)&Ws[kk * NPAD + nt * NT + 0];
            float4 w1 = *(const float4*)&Ws[kk * NPAD + nt * NT + 4];
            float4 w2 = *(const float4*)&Ws[kk * NPAD + nt * NT + 8];
            float xs[4] = {xv.x, xv.y, xv.z, xv.w};
            float ws[NT] = {w0.x, w0.y, w0.z, w0.w,
                            w1.x, w1.y, w1.z, w1.w,
                            w2.x, w2.y, w2.z, w2.w};
#pragma unroll
            for (int i = 0; i < 4; i++)
#pragma unroll
                for (int j = 0; j < NT; j++)
                    acc[i][j] = fmaf(xs[i], ws[j], acc[i][j]);
        }
    }

    // ---- bias + sigmoid ----
#pragma unroll
    for (int i = 0; i < 4; i++)
#pragma unroll
        for (int j = 0; j < NT; j++)
            acc[i][j] = fast_sigmoid(acc[i][j] + bj[j]);

    // ---- box decode (only nt==0 owns channels 0..3) ----
    if (nt == 0) {
        const float stride = (float)(8 << LEVEL);
        const float power  = (float)(1 << LEVEL);
#pragma unroll
        for (int i = 0; i < 4; i++) {
            int hwIdx = hw0 + mt * 4 + i;           // may exceed NHW; unused then
            int iy = hwIdx / NX;
            int ix = hwIdx - iy * NX;
            float d0 = acc[i][0] * 2.0f; d0 = d0 * d0 * power;
            float d1 = acc[i][1] * 2.0f; d1 = d1 * d1 * power;
            float d2 = acc[i][2] * 2.0f; d2 = d2 * d2 * power;
            float d3 = acc[i][3] * 2.0f; d3 = d3 * d3 * power;
            float x1 = ((float)ix + 1.0f - d0) * stride;
            float y1 = ((float)iy + 1.0f - d1) * stride;
            float x2 = ((float)ix + d2) * stride;
            float y2 = ((float)iy + d3) * stride;
            acc[i][0] = (x1 + x2) * 0.5f;
            acc[i][1] = (y1 + y2) * 0.5f;
            acc[i][2] = x2 - x1;
            acc[i][3] = y2 - y1;
        }
    }

    // ---- staged coalesced store, 2 waves of 64 positions ----
    float* S = smem;   // [64][SROW]
#pragma unroll
    for (int wave = 0; wave < 2; wave++) {
        __syncthreads();
        if ((mt >> 4) == wave) {
            int pl = (mt & 15) * 4;
#pragma unroll
            for (int i = 0; i < 4; i++)
#pragma unroll
                for (int j = 0; j < NT; j++) {
                    int o = nt * NT + j;
                    if (o < 85) S[(pl + i) * SROW + o] = acc[i][j];
                }
        }
        __syncthreads();
        int remain = NHW - (hw0 + wave * 64);
        int validPos = remain < 64 ? (remain < 0 ? 0 : remain) : 64;
        int total = validPos * 85;
        size_t base = ((size_t)b * 8400 + lvlOff + hw0 + wave * 64) * 85;
        for (int idx = tid; idx < total; idx += TPB) {
            int p = idx / 85;
            int o = idx - p * 85;
            out[base + idx] = S[p * SROW + o];
        }
    }
}

// level block counts: L0: ceil(6400/128)=50 per batch -> 800
//                     L1: ceil(1600/128)=13 per batch -> 208
//                     L2: ceil(400/128)=4  per batch -> 64
#define NB0 800
#define NB1 208
#define NB2 64

__global__ __launch_bounds__(TPB, 2)
void detect_fused_kernel(const float* __restrict__ x0, const float* __restrict__ x1,
                         const float* __restrict__ x2,
                         const float* __restrict__ W0, const float* __restrict__ b0,
                         const float* __restrict__ W1, const float* __restrict__ b1,
                         const float* __restrict__ W2, const float* __restrict__ b2,
                         float* __restrict__ out)
{
    __shared__ float smem[SMEM_FLOATS];
    int bid = blockIdx.x;
    if (bid < NB0) {
        run_level<256, 80, 80, 0>(x0, W0, b0, out, 0,    bid % 50, bid / 50, smem);
    } else if (bid < NB0 + NB1) {
        int r = bid - NB0;
        run_level<512, 40, 40, 1>(x1, W1, b1, out, 6400, r % 13, r / 13, smem);
    } else {
        int r = bid - (NB0 + NB1);
        run_level<1024, 20, 20, 2>(x2, W2, b2, out, 8000, r % 4, r / 4, smem);
    }
}

extern "C" void kernel_launch(void* const* d_in, const int* in_sizes, int n_in,
                              void* d_out, int out_size)
{
    const float* x0 = (const float*)d_in[0];
    const float* x1 = (const float*)d_in[1];
    const float* x2 = (const float*)d_in[2];
    const float* W0 = (const float*)d_in[3];
    const float* b0 = (const float*)d_in[4];
    const float* W1 = (const float*)d_in[5];
    const float* b1 = (const float*)d_in[6];
    const float* W2 = (const float*)d_in[7];
    const float* b2 = (const float*)d_in[8];
    float* out = (float*)d_out;

    dim3 grid(NB0 + NB1 + NB2);
    detect_fused_kernel<<<grid, TPB>>>(x0, x1, x2, W0, b0, W1, b1, W2, b2, out);
}

// round 5
// speedup vs baseline: 5.8387x; 2.7816x over previous
#include <cuda_runtime.h>
#include <cuda_bf16.h>
#include <cstdint>

// ============================================================
// Detect head via mma.sync (base ISA, works on sm_100 plain).
// Per block: D[128 pos x 96 out] = X[128 x K] * W^T, bf16x3
// compensated (Ahi*Bhi + Alo*Bhi + Ahi*Blo), fp32 accum.
// A = X tile, smem layout [k][m] (gmem-natural), ldmatrix.trans.
// B = W, prepped to [n][k] bf16 hi/lo chunks in __device__ buf.
// ============================================================

#define TPB 256
#define SROW 88

#define XS_HI 0          // 32 k-rows x 256B (swizzled)
#define XS_LO 8192
#define WS_HI 16384      // 96 n-rows x 80B
#define WS_LO 24064
#define SMEM_BYTES 31744 // union with epilogue S: 64*88*4 = 22528

__device__ __forceinline__ uint32_t smem_u32(const void* p) {
    uint32_t a;
    asm("{ .reg .u64 t; cvta.to.shared.u64 t, %1; cvt.u32.u64 %0, t; }" : "=r"(a) : "l"(p));
    return a;
}

#define LDMX4T(r, addr) \
    asm volatile("ldmatrix.sync.aligned.m8n8.x4.trans.shared.b16 {%0,%1,%2,%3}, [%4];" \
        : "=r"((r)[0]), "=r"((r)[1]), "=r"((r)[2]), "=r"((r)[3]) : "r"(addr))

#define MMA16816(d, a, b0, b1) \
    asm volatile("mma.sync.aligned.m16n8k16.row.col.f32.bf16.bf16.f32 " \
        "{%0,%1,%2,%3}, {%4,%5,%6,%7}, {%8,%9}, {%0,%1,%2,%3};" \
        : "+f"((d)[0]), "+f"((d)[1]), "+f"((d)[2]), "+f"((d)[3]) \
        : "r"((a)[0]), "r"((a)[1]), "r"((a)[2]), "r"((a)[3]), "r"(b0), "r"(b1))

// 56 chunks of 32 channels; each chunk: hi[96][32] then lo[96][32] bf16
__device__ __align__(16) __nv_bfloat16 g_Wb[56 * 2 * 96 * 32];

__global__ void prep_W(const float* __restrict__ W0, const float* __restrict__ W1,
                       const float* __restrict__ W2)
{
    int idx = blockIdx.x * blockDim.x + threadIdx.x;
    if (idx >= 56 * 96 * 32) return;
    int ch = idx / 3072, rem = idx - ch * 3072;
    int n = rem >> 5, k = rem & 31;
    const float* W; int C, cb;
    if (ch < 8)       { W = W0; C = 256;  cb = ch * 32; }
    else if (ch < 24) { W = W1; C = 512;  cb = (ch - 8) * 32; }
    else              { W = W2; C = 1024; cb = (ch - 24) * 32; }
    float v = (n < 85) ? W[(size_t)n * C + cb + k] : 0.0f;
    __nv_bfloat16 hi = __float2bfloat16(v);
    __nv_bfloat16 lo = __float2bfloat16(v - __bfloat162float(hi));
    g_Wb[(size_t)(ch * 2) * 3072 + rem]     = hi;
    g_Wb[(size_t)(ch * 2 + 1) * 3072 + rem] = lo;
}

__device__ __forceinline__ uint32_t b2u(__nv_bfloat162 h) {
    return *reinterpret_cast<uint32_t*>(&h);
}

template <int C, int NHW, int NX, int LEVEL>
__device__ __forceinline__
void run_level(const float* __restrict__ X, const float* __restrict__ bias,
               float* __restrict__ out, int lvlOff, int chBase, int b, int m0,
               char* sm, uint32_t sb)
{
    const int tid = threadIdx.x;
    const int lane = tid & 31, wid = tid >> 5;
    const int wm = wid >> 1, wn = wid & 1;
    constexpr int NCH = C / 32;
    const bool fullTile = (m0 + 128 <= NHW);
    const float* Xb = X + (size_t)b * C * NHW;

    float acc[2][6][4];
#pragma unroll
    for (int mf = 0; mf < 2; mf++)
#pragma unroll
        for (int f = 0; f < 6; f++)
#pragma unroll
            for (int e = 0; e < 4; e++) acc[mf][f][e] = 0.0f;

    for (int chk = 0; chk < NCH; chk++) {
        __syncthreads();
        // ---- stage X chunk: 32 k-rows x 128 m, fp32 -> bf16 hi/lo ----
        {
            const int c0ch = chk * 32;
#pragma unroll
            for (int it = 0; it < 4; it++) {
                int idx = tid + it * TPB;          // 0..1023
                int k = idx >> 5, m4 = idx & 31;
                const float* src = Xb + (size_t)(c0ch + k) * NHW + m0;
                float4 v;
                if (fullTile) {
                    v = *reinterpret_cast<const float4*>(src + m4 * 4);
                } else {
                    int lim = NHW - 1 - m0;
                    v.x = src[min(m4 * 4 + 0, lim)];
                    v.y = src[min(m4 * 4 + 1, lim)];
                    v.z = src[min(m4 * 4 + 2, lim)];
                    v.w = src[min(m4 * 4 + 3, lim)];
                }
                __nv_bfloat162 h0 = __floats2bfloat162_rn(v.x, v.y);
                __nv_bfloat162 h1 = __floats2bfloat162_rn(v.z, v.w);
                float2 hf0 = __bfloat1622float2(h0);
                float2 hf1 = __bfloat1622float2(h1);
                __nv_bfloat162 l0 = __floats2bfloat162_rn(v.x - hf0.x, v.y - hf0.y);
                __nv_bfloat162 l1 = __floats2bfloat162_rn(v.z - hf1.x, v.w - hf1.y);
                uint32_t off = (uint32_t)(k * 256 + ((m4 * 8) ^ ((k & 7) << 4)));
                *reinterpret_cast<uint2*>(sm + XS_HI + off) = make_uint2(b2u(h0), b2u(h1));
                *reinterpret_cast<uint2*>(sm + XS_LO + off) = make_uint2(b2u(l0), b2u(l1));
            }
        }
        // ---- stage W chunk: [96][32] bf16 hi/lo -> rows padded to 80B ----
        {
            const uint4* srcHi = reinterpret_cast<const uint4*>(
                &g_Wb[(size_t)((chBase + chk) * 2) * 3072]);
            const uint4* srcLo = srcHi + 384;
#pragma unroll
            for (int it = 0; it < 2; it++) {
                int idx = tid + it * TPB;
                if (idx < 384) {
                    int n = idx >> 2, k16 = idx & 3;
                    *reinterpret_cast<uint4*>(sm + WS_HI + n * 80 + k16 * 16) = srcHi[idx];
                    *reinterpret_cast<uint4*>(sm + WS_LO + n * 80 + k16 * 16) = srcLo[idx];
                }
            }
        }
        __syncthreads();

        // ---- MMA: 2 k16 steps, 3 compensated passes ----
#pragma unroll
        for (int ks = 0; ks < 2; ks++) {
            uint32_t ahi[2][4], alo[2][4];
            const int mat = lane >> 3, r = lane & 7;
#pragma unroll
            for (int mf = 0; mf < 2; mf++) {
                int k = ks * 16 + ((mat >> 1) << 3) + r;
                int mb = (wm * 32 + mf * 16 + ((mat & 1) << 3)) * 2;
                uint32_t aoff = (uint32_t)(k * 256 + (mb ^ ((k & 7) << 4)));
                LDMX4T(ahi[mf], sb + XS_HI + aoff);
                LDMX4T(alo[mf], sb + XS_LO + aoff);
            }
#pragma unroll
            for (int f = 0; f < 6; f++) {
                int n = wn * 48 + f * 8 + (lane >> 2);
                uint32_t boff = (uint32_t)(n * 80 + (ks * 16 + (lane & 3) * 2) * 2);
                uint32_t bh0 = *reinterpret_cast<const uint32_t*>(sm + WS_HI + boff);
                uint32_t bh1 = *reinterpret_cast<const uint32_t*>(sm + WS_HI + boff + 16);
                uint32_t bl0 = *reinterpret_cast<const uint32_t*>(sm + WS_LO + boff);
                uint32_t bl1 = *reinterpret_cast<const uint32_t*>(sm + WS_LO + boff + 16);
#pragma unroll
                for (int mf = 0; mf < 2; mf++) {
                    MMA16816(acc[mf][f], ahi[mf], bh0, bh1);
                    MMA16816(acc[mf][f], alo[mf], bh0, bh1);
                    MMA16816(acc[mf][f], ahi[mf], bl0, bl1);
                }
            }
        }
    }

    // ---- bias + sigmoid ----
    const int g = lane >> 2, c0 = lane & 3;
#pragma unroll
    for (int f = 0; f < 6; f++) {
        int nb = wn * 48 + f * 8 + c0 * 2;
        float bv0 = (nb < 85) ? __ldg(&bias[nb]) : 0.0f;
        float bv1 = (nb + 1 < 85) ? __ldg(&bias[nb + 1]) : 0.0f;
#pragma unroll
        for (int mf = 0; mf < 2; mf++)
#pragma unroll
            for (int h = 0; h < 2; h++) {
                float p0 = acc[mf][f][h * 2 + 0] + bv0;
                float p1 = acc[mf][f][h * 2 + 1] + bv1;
                acc[mf][f][h * 2 + 0] = __fdividef(1.0f, 1.0f + __expf(-p0));
                acc[mf][f][h * 2 + 1] = __fdividef(1.0f, 1.0f + __expf(-p1));
            }
    }

    // ---- box decode (channels 0..3 live in wn==0, f==0, c0<2) ----
    if (wn == 0) {
        const float power = (float)(1 << LEVEL);
        const float strd  = (float)(8 << LEVEL);
#pragma unroll
        for (int mf = 0; mf < 2; mf++)
#pragma unroll
            for (int h = 0; h < 2; h++) {
                float s0 = acc[mf][0][h * 2 + 0];
                float s1 = acc[mf][0][h * 2 + 1];
                float q0 = 4.0f * s0 * s0 * power;
                float q1 = 4.0f * s1 * s1 * power;
                float p0 = __shfl_xor_sync(0xffffffffu, q0, 1);
                float p1 = __shfl_xor_sync(0xffffffffu, q1, 1);
                float dx1 = (c0 == 0) ? q0 : p0;
                float dy1 = (c0 == 0) ? q1 : p1;
                float dx2 = (c0 == 0) ? p0 : q0;
                float dy2 = (c0 == 0) ? p1 : q1;
                int pos = m0 + wm * 32 + mf * 16 + h * 8 + g;
                int iy = pos / NX, ix = pos - iy * NX;
                float x1 = ((float)ix + 1.0f - dx1) * strd;
                float y1 = ((float)iy + 1.0f - dy1) * strd;
                float x2 = ((float)ix + dx2) * strd;
                float y2 = ((float)iy + dy2) * strd;
                if (c0 == 0) {
                    acc[mf][0][h * 2 + 0] = 0.5f * (x1 + x2);
                    acc[mf][0][h * 2 + 1] = 0.5f * (y1 + y2);
                } else if (c0 == 1) {
                    acc[mf][0][h * 2 + 0] = x2 - x1;
                    acc[mf][0][h * 2 + 1] = y2 - y1;
                }
            }
    }

    // ---- staged coalesced store: 2 waves of 64 positions ----
    float* S = reinterpret_cast<float*>(sm);
#pragma unroll
    for (int w = 0; w < 2; w++) {
        __syncthreads();
        if ((wm >> 1) == w) {
            int mbase = (wm & 1) * 32;
#pragma unroll
            for (int mf = 0; mf < 2; mf++)
#pragma unroll
                for (int h = 0; h < 2; h++) {
                    int mrow = mbase + mf * 16 + h * 8 + g;
#pragma unroll
                    for (int f = 0; f < 6; f++) {
                        int n = wn * 48 + f * 8 + c0 * 2;
                        if (n + 1 < 85)
                            *reinterpret_cast<float2*>(&S[mrow * SROW + n]) =
                                make_float2(acc[mf][f][h * 2], acc[mf][f][h * 2 + 1]);
                        else if (n < 85)
                            S[mrow * SROW + n] = acc[mf][f][h * 2];
                    }
                }
        }
        __syncthreads();
        int valid = NHW - (m0 + w * 64);
        valid = valid < 0 ? 0 : (valid > 64 ? 64 : valid);
        int total = valid * 85;
        float* ob = out + ((size_t)b * 8400 + lvlOff + m0 + w * 64) * 85;
        for (int i = tid; i < total; i += TPB) {
            int p = i / 85, o = i - p * 85;
            ob[i] = S[p * SROW + o];
        }
    }
}

// grid order: L2 (longest, 32 chunks) first, then L1, then L0
__global__ __launch_bounds__(TPB, 2)
void detect_tc(const float* __restrict__ x0, const float* __restrict__ x1,
               const float* __restrict__ x2,
               const float* __restrict__ b0, const float* __restrict__ b1,
               const float* __restrict__ b2, float* __restrict__ out)
{
    __shared__ __align__(1024) char sm[SMEM_BYTES];
    uint32_t sb = smem_u32(sm);
    int bid = blockIdx.x;
    if (bid < 64) {                      // L2: 4 tiles x 16 batch
        int b = bid >> 2, t = bid & 3;
        run_level<1024, 400, 20, 2>(x2, b2, out, 8000, 24, b, t * 128, sm, sb);
    } else if (bid < 272) {              // L1: 13 tiles x 16 batch
        int q = bid - 64;
        int b = q / 13, t = q - b * 13;
        run_level<512, 1600, 40, 1>(x1, b1, out, 6400, 8, b, t * 128, sm, sb);
    } else {                             // L0: 50 tiles x 16 batch
        int q = bid - 272;
        int b = q / 50, t = q - b * 50;
        run_level<256, 6400, 80, 0>(x0, b0, out, 0, 0, b, t * 128, sm, sb);
    }
}

extern "C" void kernel_launch(void* const* d_in, const int* in_sizes, int n_in,
                              void* d_out, int out_size)
{
    const float* x0 = (const float*)d_in[0];
    const float* x1 = (const float*)d_in[1];
    const float* x2 = (const float*)d_in[2];
    const float* W0 = (const float*)d_in[3];
    const float* b0 = (const float*)d_in[4];
    const float* W1 = (const float*)d_in[5];
    const float* b1 = (const float*)d_in[6];
    const float* W2 = (const float*)d_in[7];
    const float* b2 = (const float*)d_in[8];
    float* out = (float*)d_out;

    prep_W<<<(56 * 96 * 32 + 255) / 256, 256>>>(W0, W1, W2);
    detect_tc<<<64 + 208 + 800, TPB>>>(x0, x1, x2, b0, b1, b2, out);
}

// round 6
// speedup vs baseline: 7.0517x; 1.2078x over previous
#include <cuda_runtime.h>
#include <cuda_bf16.h>
#include <cstdint>

// ============================================================
// Detect head via mma.sync (base ISA). bf16x3 compensated GEMM
// D[128 pos x 96 out], fp32 accum. R6: software-pipelined K loop
// (X prefetched in registers, W staged via cp.async).
// ============================================================

#define TPB 256
#define SROW 88

#define XS_HI 0          // 32 k-rows x 256B (swizzled)
#define XS_LO 8192
#define WS_HI 16384      // 96 n-rows x 80B
#define WS_LO 24064
#define SMEM_BYTES 31744

__device__ __forceinline__ uint32_t smem_u32(const void* p) {
    uint32_t a;
    asm("{ .reg .u64 t; cvta.to.shared.u64 t, %1; cvt.u32.u64 %0, t; }" : "=r"(a) : "l"(p));
    return a;
}

#define LDMX4T(r, addr) \
    asm volatile("ldmatrix.sync.aligned.m8n8.x4.trans.shared.b16 {%0,%1,%2,%3}, [%4];" \
        : "=r"((r)[0]), "=r"((r)[1]), "=r"((r)[2]), "=r"((r)[3]) : "r"(addr))

#define MMA16816(d, a, b0, b1) \
    asm volatile("mma.sync.aligned.m16n8k16.row.col.f32.bf16.bf16.f32 " \
        "{%0,%1,%2,%3}, {%4,%5,%6,%7}, {%8,%9}, {%0,%1,%2,%3};" \
        : "+f"((d)[0]), "+f"((d)[1]), "+f"((d)[2]), "+f"((d)[3]) \
        : "r"((a)[0]), "r"((a)[1]), "r"((a)[2]), "r"((a)[3]), "r"(b0), "r"(b1))

#define CP_ASYNC16(dst, src) \
    asm volatile("cp.async.ca.shared.global [%0], [%1], 16;" :: "r"(dst), "l"(src))
#define CP_COMMIT() asm volatile("cp.async.commit_group;" ::: "memory")
#define CP_WAIT0()  asm volatile("cp.async.wait_group 0;" ::: "memory")

// 56 chunks of 32 channels; each chunk: hi[96][32] then lo[96][32] bf16 (contiguous)
__device__ __align__(16) __nv_bfloat16 g_Wb[56 * 2 * 96 * 32];

__global__ void prep_W(const float* __restrict__ W0, const float* __restrict__ W1,
                       const float* __restrict__ W2)
{
    int idx = blockIdx.x * blockDim.x + threadIdx.x;
    if (idx >= 56 * 96 * 32) return;
    int ch = idx / 3072, rem = idx - ch * 3072;
    int n = rem >> 5, k = rem & 31;
    const float* W; int C, cb;
    if (ch < 8)       { W = W0; C = 256;  cb = ch * 32; }
    else if (ch < 24) { W = W1; C = 512;  cb = (ch - 8) * 32; }
    else              { W = W2; C = 1024; cb = (ch - 24) * 32; }
    float v = (n < 85) ? W[(size_t)n * C + cb + k] : 0.0f;
    __nv_bfloat16 hi = __float2bfloat16(v);
    __nv_bfloat16 lo = __float2bfloat16(v - __bfloat162float(hi));
    g_Wb[(size_t)(ch * 2) * 3072 + rem]     = hi;
    g_Wb[(size_t)(ch * 2 + 1) * 3072 + rem] = lo;
}

__device__ __forceinline__ uint32_t b2u(__nv_bfloat162 h) {
    return *reinterpret_cast<uint32_t*>(&h);
}

template <int NHW>
__device__ __forceinline__
void load_x_regs(float4 (&v)[4], const float* __restrict__ Xb, int c0ch, int m0,
                 bool fullTile, int tid)
{
#pragma unroll
    for (int it = 0; it < 4; it++) {
        int idx = tid + it * TPB;
        int k = idx >> 5, m4 = idx & 31;
        const float* src = Xb + (size_t)(c0ch + k) * NHW + m0;
        if (fullTile) {
            v[it] = *reinterpret_cast<const float4*>(src + m4 * 4);
        } else {
            int lim = NHW - 1 - m0;
            v[it].x = src[min(m4 * 4 + 0, lim)];
            v[it].y = src[min(m4 * 4 + 1, lim)];
            v[it].z = src[min(m4 * 4 + 2, lim)];
            v[it].w = src[min(m4 * 4 + 3, lim)];
        }
    }
}

template <int C, int NHW, int NX, int LEVEL>
__device__ __forceinline__
void run_level(const float* __restrict__ X, const float* __restrict__ bias,
               float* __restrict__ out, int lvlOff, int chBase, int b, int m0,
               char* sm, uint32_t sb)
{
    const int tid = threadIdx.x;
    const int lane = tid & 31, wid = tid >> 5;
    const int wm = wid >> 1, wn = wid & 1;
    constexpr int NCH = C / 32;
    const bool fullTile = (m0 + 128 <= NHW);
    const float* Xb = X + (size_t)b * C * NHW;

    float acc[2][6][4];
#pragma unroll
    for (int mf = 0; mf < 2; mf++)
#pragma unroll
        for (int f = 0; f < 6; f++)
#pragma unroll
            for (int e = 0; e < 4; e++) acc[mf][f][e] = 0.0f;

    // W cp.async targets for this thread (3 x 16B per chunk)
    uint32_t wdst[3];
#pragma unroll
    for (int it = 0; it < 3; it++) {
        int idx = tid + it * TPB;              // 0..767
        int j = (idx < 384) ? idx : idx - 384;
        int n = j >> 2, k16 = j & 3;
        wdst[it] = sb + ((idx < 384) ? WS_HI : WS_LO) + n * 80 + k16 * 16;
    }

    // ---- prologue: prefetch chunk 0 ----
    float4 v[4];
    load_x_regs<NHW>(v, Xb, 0, m0, fullTile, tid);

    for (int chk = 0; chk < NCH; chk++) {
        __syncthreads();   // previous MMA done reading smem

        // ---- W chunk via cp.async (bf16 direct) ----
        {
            const uint4* wsrc = reinterpret_cast<const uint4*>(
                &g_Wb[(size_t)((chBase + chk) * 2) * 3072]);
#pragma unroll
            for (int it = 0; it < 3; it++)
                CP_ASYNC16(wdst[it], wsrc + tid + it * TPB);
            CP_COMMIT();
        }

        // ---- convert current X regs -> smem (hi/lo, swizzled) ----
#pragma unroll
        for (int it = 0; it < 4; it++) {
            int idx = tid + it * TPB;
            int k = idx >> 5, m4 = idx & 31;
            float4 q = v[it];
            __nv_bfloat162 h0 = __floats2bfloat162_rn(q.x, q.y);
            __nv_bfloat162 h1 = __floats2bfloat162_rn(q.z, q.w);
            float2 hf0 = __bfloat1622float2(h0);
            float2 hf1 = __bfloat1622float2(h1);
            __nv_bfloat162 l0 = __floats2bfloat162_rn(q.x - hf0.x, q.y - hf0.y);
            __nv_bfloat162 l1 = __floats2bfloat162_rn(q.z - hf1.x, q.w - hf1.y);
            uint32_t off = (uint32_t)(k * 256 + ((m4 * 8) ^ ((k & 7) << 4)));
            *reinterpret_cast<uint2*>(sm + XS_HI + off) = make_uint2(b2u(h0), b2u(h1));
            *reinterpret_cast<uint2*>(sm + XS_LO + off) = make_uint2(b2u(l0), b2u(l1));
        }

        // ---- prefetch next X chunk (latency hidden under MMA) ----
        if (chk + 1 < NCH)
            load_x_regs<NHW>(v, Xb, (chk + 1) * 32, m0, fullTile, tid);

        CP_WAIT0();
        __syncthreads();

        // ---- MMA: 2 k16 steps, 3 compensated passes ----
#pragma unroll
        for (int ks = 0; ks < 2; ks++) {
            uint32_t ahi[2][4], alo[2][4];
            const int mat = lane >> 3, r = lane & 7;
#pragma unroll
            for (int mf = 0; mf < 2; mf++) {
                int k = ks * 16 + ((mat >> 1) << 3) + r;
                int mb = (wm * 32 + mf * 16 + ((mat & 1) << 3)) * 2;
                uint32_t aoff = (uint32_t)(k * 256 + (mb ^ ((k & 7) << 4)));
                LDMX4T(ahi[mf], sb + XS_HI + aoff);
                LDMX4T(alo[mf], sb + XS_LO + aoff);
            }
#pragma unroll
            for (int f = 0; f < 6; f++) {
                int n = wn * 48 + f * 8 + (lane >> 2);
                uint32_t boff = (uint32_t)(n * 80 + (ks * 16 + (lane & 3) * 2) * 2);
                uint32_t bh0 = *reinterpret_cast<const uint32_t*>(sm + WS_HI + boff);
                uint32_t bh1 = *reinterpret_cast<const uint32_t*>(sm + WS_HI + boff + 16);
                uint32_t bl0 = *reinterpret_cast<const uint32_t*>(sm + WS_LO + boff);
                uint32_t bl1 = *reinterpret_cast<const uint32_t*>(sm + WS_LO + boff + 16);
#pragma unroll
                for (int mf = 0; mf < 2; mf++) {
                    MMA16816(acc[mf][f], ahi[mf], bh0, bh1);
                    MMA16816(acc[mf][f], alo[mf], bh0, bh1);
                    MMA16816(acc[mf][f], ahi[mf], bl0, bl1);
                }
            }
        }
    }

    // ---- bias + sigmoid ----
    const int g = lane >> 2, c0 = lane & 3;
#pragma unroll
    for (int f = 0; f < 6; f++) {
        int nb = wn * 48 + f * 8 + c0 * 2;
        float bv0 = (nb < 85) ? __ldg(&bias[nb]) : 0.0f;
        float bv1 = (nb + 1 < 85) ? __ldg(&bias[nb + 1]) : 0.0f;
#pragma unroll
        for (int mf = 0; mf < 2; mf++)
#pragma unroll
            for (int h = 0; h < 2; h++) {
                float p0 = acc[mf][f][h * 2 + 0] + bv0;
                float p1 = acc[mf][f][h * 2 + 1] + bv1;
                acc[mf][f][h * 2 + 0] = __fdividef(1.0f, 1.0f + __expf(-p0));
                acc[mf][f][h * 2 + 1] = __fdividef(1.0f, 1.0f + __expf(-p1));
            }
    }

    // ---- box decode (channels 0..3 live in wn==0, f==0, c0<2) ----
    if (wn == 0) {
        const float power = (float)(1 << LEVEL);
        const float strd  = (float)(8 << LEVEL);
#pragma unroll
        for (int mf = 0; mf < 2; mf++)
#pragma unroll
            for (int h = 0; h < 2; h++) {
                float s0 = acc[mf][0][h * 2 + 0];
                float s1 = acc[mf][0][h * 2 + 1];
                float q0 = 4.0f * s0 * s0 * power;
                float q1 = 4.0f * s1 * s1 * power;
                float p0 = __shfl_xor_sync(0xffffffffu, q0, 1);
                float p1 = __shfl_xor_sync(0xffffffffu, q1, 1);
                float dx1 = (c0 == 0) ? q0 : p0;
                float dy1 = (c0 == 0) ? q1 : p1;
                float dx2 = (c0 == 0) ? p0 : q0;
                float dy2 = (c0 == 0) ? p1 : q1;
                int pos = m0 + wm * 32 + mf * 16 + h * 8 + g;
                int iy = pos / NX, ix = pos - iy * NX;
                float x1 = ((float)ix + 1.0f - dx1) * strd;
                float y1 = ((float)iy + 1.0f - dy1) * strd;
                float x2 = ((float)ix + dx2) * strd;
                float y2 = ((float)iy + dy2) * strd;
                if (c0 == 0) {
                    acc[mf][0][h * 2 + 0] = 0.5f * (x1 + x2);
                    acc[mf][0][h * 2 + 1] = 0.5f * (y1 + y2);
                } else if (c0 == 1) {
                    acc[mf][0][h * 2 + 0] = x2 - x1;
                    acc[mf][0][h * 2 + 1] = y2 - y1;
                }
            }
    }

    // ---- staged coalesced store: 2 waves of 64 positions ----
    float* S = reinterpret_cast<float*>(sm);
#pragma unroll
    for (int w = 0; w < 2; w++) {
        __syncthreads();
        if ((wm >> 1) == w) {
            int mbase = (wm & 1) * 32;
#pragma unroll
            for (int mf = 0; mf < 2; mf++)
#pragma unroll
                for (int h = 0; h < 2; h++) {
                    int mrow = mbase + mf * 16 + h * 8 + g;
#pragma unroll
                    for (int f = 0; f < 6; f++) {
                        int n = wn * 48 + f * 8 + c0 * 2;
                        if (n + 1 < 85)
                            *reinterpret_cast<float2*>(&S[mrow * SROW + n]) =
                                make_float2(acc[mf][f][h * 2], acc[mf][f][h * 2 + 1]);
                        else if (n < 85)
                            S[mrow * SROW + n] = acc[mf][f][h * 2];
                    }
                }
        }
        __syncthreads();
        int valid = NHW - (m0 + w * 64);
        valid = valid < 0 ? 0 : (valid > 64 ? 64 : valid);
        int total = valid * 85;
        float* ob = out + ((size_t)b * 8400 + lvlOff + m0 + w * 64) * 85;
        for (int i = tid; i < total; i += TPB) {
            int p = i / 85, o = i - p * 85;
            ob[i] = S[p * SROW + o];
        }
    }
}

// grid order: L2 (longest, 32 chunks) first, then L1, then L0
__global__ __launch_bounds__(TPB, 2)
void detect_tc(const float* __restrict__ x0, const float* __restrict__ x1,
               const float* __restrict__ x2,
               const float* __restrict__ b0, const float* __restrict__ b1,
               const float* __restrict__ b2, float* __restrict__ out)
{
    __shared__ __align__(1024) char sm[SMEM_BYTES];
    uint32_t sb = smem_u32(sm);
    int bid = blockIdx.x;
    if (bid < 64) {                      // L2: 4 tiles x 16 batch
        int b = bid >> 2, t = bid & 3;
        run_level<1024, 400, 20, 2>(x2, b2, out, 8000, 24, b, t * 128, sm, sb);
    } else if (bid < 272) {              // L1: 13 tiles x 16 batch
        int q = bid - 64;
        int b = q / 13, t = q - b * 13;
        run_level<512, 1600, 40, 1>(x1, b1, out, 6400, 8, b, t * 128, sm, sb);
    } else {                             // L0: 50 tiles x 16 batch
        int q = bid - 272;
        int b = q / 50, t = q - b * 50;
        run_level<256, 6400, 80, 0>(x0, b0, out, 0, 0, b, t * 128, sm, sb);
    }
}

extern "C" void kernel_launch(void* const* d_in, const int* in_sizes, int n_in,
                              void* d_out, int out_size)
{
    const float* x0 = (const float*)d_in[0];
    const float* x1 = (const float*)d_in[1];
    const float* x2 = (const float*)d_in[2];
    const float* W0 = (const float*)d_in[3];
    const float* b0 = (const float*)d_in[4];
    const float* W1 = (const float*)d_in[5];
    const float* b1 = (const float*)d_in[6];
    const float* W2 = (const float*)d_in[7];
    const float* b2 = (const float*)d_in[8];
    float* out = (float*)d_out;

    prep_W<<<(56 * 96 * 32 + 255) / 256, 256>>>(W0, W1, W2);
    detect_tc<<<64 + 208 + 800, TPB>>>(x0, x1, x2, b0, b1, b2, out);
}

// round 7
// speedup vs baseline: 11.2614x; 1.5970x over previous
#include <cuda_runtime.h>
#include <cuda_fp16.h>
#include <cstdint>

// ============================================================
// Detect head via mma.sync (base ISA). fp16 single-pass GEMM
// D[128 pos x 96 out], fp32 accum. Software-pipelined K loop
// (X prefetched in registers, W staged via cp.async).
// Precision: fp16 operands, fp32 accum -> rel_err ~6e-5 (calibrated
// from bf16x3 run: damping ~0.16 on logit-relative error).
// ============================================================

#define TPB 256
#define SROW 88

#define XS_OFF 0          // 32 k-rows x 256B (swizzled fp16)
#define WS_OFF 8192       // 96 n-rows x 80B (fp16, 64B data + pad)
#define SMEM_BYTES 22528  // union with epilogue S: 64*88*4

__device__ __forceinline__ uint32_t smem_u32(const void* p) {
    uint32_t a;
    asm("{ .reg .u64 t; cvta.to.shared.u64 t, %1; cvt.u32.u64 %0, t; }" : "=r"(a) : "l"(p));
    return a;
}

#define LDMX4T(r, addr) \
    asm volatile("ldmatrix.sync.aligned.m8n8.x4.trans.shared.b16 {%0,%1,%2,%3}, [%4];" \
        : "=r"((r)[0]), "=r"((r)[1]), "=r"((r)[2]), "=r"((r)[3]) : "r"(addr))

#define MMA16816(d, a, b0, b1) \
    asm volatile("mma.sync.aligned.m16n8k16.row.col.f32.f16.f16.f32 " \
        "{%0,%1,%2,%3}, {%4,%5,%6,%7}, {%8,%9}, {%0,%1,%2,%3};" \
        : "+f"((d)[0]), "+f"((d)[1]), "+f"((d)[2]), "+f"((d)[3]) \
        : "r"((a)[0]), "r"((a)[1]), "r"((a)[2]), "r"((a)[3]), "r"(b0), "r"(b1))

#define CP_ASYNC16(dst, src) \
    asm volatile("cp.async.ca.shared.global [%0], [%1], 16;" :: "r"(dst), "l"(src))
#define CP_COMMIT() asm volatile("cp.async.commit_group;" ::: "memory")
#define CP_WAIT0()  asm volatile("cp.async.wait_group 0;" ::: "memory")

// 56 chunks of 32 channels: [96 n][32 k] fp16 each
__device__ __align__(16) __half g_Wh[56 * 96 * 32];

__global__ void prep_W(const float* __restrict__ W0, const float* __restrict__ W1,
                       const float* __restrict__ W2)
{
    int idx = blockIdx.x * blockDim.x + threadIdx.x;
    if (idx >= 56 * 96 * 32) return;
    int ch = idx / 3072, rem = idx - ch * 3072;
    int n = rem >> 5, k = rem & 31;
    const float* W; int C, cb;
    if (ch < 8)       { W = W0; C = 256;  cb = ch * 32; }
    else if (ch < 24) { W = W1; C = 512;  cb = (ch - 8) * 32; }
    else              { W = W2; C = 1024; cb = (ch - 24) * 32; }
    float v = (n < 85) ? W[(size_t)n * C + cb + k] : 0.0f;
    g_Wh[idx] = __float2half(v);
}

__device__ __forceinline__ uint32_t h2u(__half2 h) {
    return *reinterpret_cast<uint32_t*>(&h);
}

template <int NHW>
__device__ __forceinline__
void load_x_regs(float4 (&v)[4], const float* __restrict__ Xb, int c0ch, int m0,
                 bool fullTile, int tid)
{
#pragma unroll
    for (int it = 0; it < 4; it++) {
        int idx = tid + it * TPB;
        int k = idx >> 5, m4 = idx & 31;
        const float* src = Xb + (size_t)(c0ch + k) * NHW + m0;
        if (fullTile) {
            v[it] = *reinterpret_cast<const float4*>(src + m4 * 4);
        } else {
            int lim = NHW - 1 - m0;
            v[it].x = src[min(m4 * 4 + 0, lim)];
            v[it].y = src[min(m4 * 4 + 1, lim)];
            v[it].z = src[min(m4 * 4 + 2, lim)];
            v[it].w = src[min(m4 * 4 + 3, lim)];
        }
    }
}

template <int C, int NHW, int NX, int LEVEL>
__device__ __forceinline__
void run_level(const float* __restrict__ X, const float* __restrict__ bias,
               float* __restrict__ out, int lvlOff, int chBase, int b, int m0,
               char* sm, uint32_t sb)
{
    const int tid = threadIdx.x;
    const int lane = tid & 31, wid = tid >> 5;
    const int wm = wid >> 1, wn = wid & 1;
    constexpr int NCH = C / 32;
    const bool fullTile = (m0 + 128 <= NHW);
    const float* Xb = X + (size_t)b * C * NHW;

    float acc[2][6][4];
#pragma unroll
    for (int mf = 0; mf < 2; mf++)
#pragma unroll
        for (int f = 0; f < 6; f++)
#pragma unroll
            for (int e = 0; e < 4; e++) acc[mf][f][e] = 0.0f;

    // W cp.async target for this thread (96 rows x 4 x 16B = 384 units)
    uint32_t wdst0 = 0, wdst1 = 0;
    {
        int n = tid >> 2, k16 = tid & 3;
        wdst0 = sb + WS_OFF + n * 80 + k16 * 16;
        if (tid < 128) {
            int idx = tid + 256;
            n = idx >> 2; k16 = idx & 3;
            wdst1 = sb + WS_OFF + n * 80 + k16 * 16;
        }
    }

    // ---- prologue: prefetch chunk 0 ----
    float4 v[4];
    load_x_regs<NHW>(v, Xb, 0, m0, fullTile, tid);

    for (int chk = 0; chk < NCH; chk++) {
        __syncthreads();   // previous MMA done reading smem

        // ---- W chunk via cp.async (fp16 direct, hi only) ----
        {
            const uint4* wsrc = reinterpret_cast<const uint4*>(
                &g_Wh[(size_t)(chBase + chk) * 3072]);
            CP_ASYNC16(wdst0, wsrc + tid);
            if (tid < 128) CP_ASYNC16(wdst1, wsrc + tid + 256);
            CP_COMMIT();
        }

        // ---- convert current X regs -> smem (fp16, swizzled) ----
#pragma unroll
        for (int it = 0; it < 4; it++) {
            int idx = tid + it * TPB;
            int k = idx >> 5, m4 = idx & 31;
            float4 q = v[it];
            __half2 h0 = __floats2half2_rn(q.x, q.y);
            __half2 h1 = __floats2half2_rn(q.z, q.w);
            uint32_t off = (uint32_t)(k * 256 + ((m4 * 8) ^ ((k & 7) << 4)));
            *reinterpret_cast<uint2*>(sm + XS_OFF + off) = make_uint2(h2u(h0), h2u(h1));
        }

        // ---- prefetch next X chunk (latency hidden under MMA) ----
        if (chk + 1 < NCH)
            load_x_regs<NHW>(v, Xb, (chk + 1) * 32, m0, fullTile, tid);

        CP_WAIT0();
        __syncthreads();

        // ---- MMA: 2 k16 steps, single fp16 pass ----
#pragma unroll
        for (int ks = 0; ks < 2; ks++) {
            uint32_t af[2][4];
            const int mat = lane >> 3, r = lane & 7;
#pragma unroll
            for (int mf = 0; mf < 2; mf++) {
                int k = ks * 16 + ((mat >> 1) << 3) + r;
                int mb = (wm * 32 + mf * 16 + ((mat & 1) << 3)) * 2;
                uint32_t aoff = (uint32_t)(k * 256 + (mb ^ ((k & 7) << 4)));
                LDMX4T(af[mf], sb + XS_OFF + aoff);
            }
#pragma unroll
            for (int f = 0; f < 6; f++) {
                int n = wn * 48 + f * 8 + (lane >> 2);
                uint32_t boff = (uint32_t)(n * 80 + (ks * 16 + (lane & 3) * 2) * 2);
                uint32_t b0 = *reinterpret_cast<const uint32_t*>(sm + WS_OFF + boff);
                uint32_t b1 = *reinterpret_cast<const uint32_t*>(sm + WS_OFF + boff + 16);
#pragma unroll
                for (int mf = 0; mf < 2; mf++)
                    MMA16816(acc[mf][f], af[mf], b0, b1);
            }
        }
    }

    // ---- bias + sigmoid ----
    const int g = lane >> 2, c0 = lane & 3;
#pragma unroll
    for (int f = 0; f < 6; f++) {
        int nb = wn * 48 + f * 8 + c0 * 2;
        float bv0 = (nb < 85) ? __ldg(&bias[nb]) : 0.0f;
        float bv1 = (nb + 1 < 85) ? __ldg(&bias[nb + 1]) : 0.0f;
#pragma unroll
        for (int mf = 0; mf < 2; mf++)
#pragma unroll
            for (int h = 0; h < 2; h++) {
                float p0 = acc[mf][f][h * 2 + 0] + bv0;
                float p1 = acc[mf][f][h * 2 + 1] + bv1;
                acc[mf][f][h * 2 + 0] = __fdividef(1.0f, 1.0f + __expf(-p0));
                acc[mf][f][h * 2 + 1] = __fdividef(1.0f, 1.0f + __expf(-p1));
            }
    }

    // ---- box decode (channels 0..3 live in wn==0, f==0, c0<2) ----
    if (wn == 0) {
        const float power = (float)(1 << LEVEL);
        const float strd  = (float)(8 << LEVEL);
#pragma unroll
        for (int mf = 0; mf < 2; mf++)
#pragma unroll
            for (int h = 0; h < 2; h++) {
                float s0 = acc[mf][0][h * 2 + 0];
                float s1 = acc[mf][0][h * 2 + 1];
                float q0 = 4.0f * s0 * s0 * power;
                float q1 = 4.0f * s1 * s1 * power;
                float p0 = __shfl_xor_sync(0xffffffffu, q0, 1);
                float p1 = __shfl_xor_sync(0xffffffffu, q1, 1);
                float dx1 = (c0 == 0) ? q0 : p0;
                float dy1 = (c0 == 0) ? q1 : p1;
                float dx2 = (c0 == 0) ? p0 : q0;
                float dy2 = (c0 == 0) ? p1 : q1;
                int pos = m0 + wm * 32 + mf * 16 + h * 8 + g;
                int iy = pos / NX, ix = pos - iy * NX;
                float x1 = ((float)ix + 1.0f - dx1) * strd;
                float y1 = ((float)iy + 1.0f - dy1) * strd;
                float x2 = ((float)ix + dx2) * strd;
                float y2 = ((float)iy + dy2) * strd;
                if (c0 == 0) {
                    acc[mf][0][h * 2 + 0] = 0.5f * (x1 + x2);
                    acc[mf][0][h * 2 + 1] = 0.5f * (y1 + y2);
                } else if (c0 == 1) {
                    acc[mf][0][h * 2 + 0] = x2 - x1;
                    acc[mf][0][h * 2 + 1] = y2 - y1;
                }
            }
    }

    // ---- staged coalesced store: 2 waves of 64 positions ----
    float* S = reinterpret_cast<float*>(sm);
#pragma unroll
    for (int w = 0; w < 2; w++) {
        __syncthreads();
        if ((wm >> 1) == w) {
            int mbase = (wm & 1) * 32;
#pragma unroll
            for (int mf = 0; mf < 2; mf++)
#pragma unroll
                for (int h = 0; h < 2; h++) {
                    int mrow = mbase + mf * 16 + h * 8 + g;
#pragma unroll
                    for (int f = 0; f < 6; f++) {
                        int n = wn * 48 + f * 8 + c0 * 2;
                        if (n + 1 < 85)
                            *reinterpret_cast<float2*>(&S[mrow * SROW + n]) =
                                make_float2(acc[mf][f][h * 2], acc[mf][f][h * 2 + 1]);
                        else if (n < 85)
                            S[mrow * SROW + n] = acc[mf][f][h * 2];
                    }
                }
        }
        __syncthreads();
        int valid = NHW - (m0 + w * 64);
        valid = valid < 0 ? 0 : (valid > 64 ? 64 : valid);
        int total = valid * 85;
        float* ob = out + ((size_t)b * 8400 + lvlOff + m0 + w * 64) * 85;
        for (int i = tid; i < total; i += TPB) {
            int p = i / 85, o = i - p * 85;
            ob[i] = S[p * SROW + o];
        }
    }
}

// grid order: L2 (longest, 32 chunks) first, then L1, then L0
__global__ __launch_bounds__(TPB, 2)
void detect_tc(const float* __restrict__ x0, const float* __restrict__ x1,
               const float* __restrict__ x2,
               const float* __restrict__ b0, const float* __restrict__ b1,
               const float* __restrict__ b2, float* __restrict__ out)
{
    __shared__ __align__(1024) char sm[SMEM_BYTES];
    uint32_t sb = smem_u32(sm);
    int bid = blockIdx.x;
    if (bid < 64) {                      // L2: 4 tiles x 16 batch
        int b = bid >> 2, t = bid & 3;
        run_level<1024, 400, 20, 2>(x2, b2, out, 8000, 24, b, t * 128, sm, sb);
    } else if (bid < 272) {              // L1: 13 tiles x 16 batch
        int q = bid - 64;
        int b = q / 13, t = q - b * 13;
        run_level<512, 1600, 40, 1>(x1, b1, out, 6400, 8, b, t * 128, sm, sb);
    } else {                             // L0: 50 tiles x 16 batch
        int q = bid - 272;
        int b = q / 50, t = q - b * 50;
        run_level<256, 6400, 80, 0>(x0, b0, out, 0, 0, b, t * 128, sm, sb);
    }
}

extern "C" void kernel_launch(void* const* d_in, const int* in_sizes, int n_in,
                              void* d_out, int out_size)
{
    const float* x0 = (const float*)d_in[0];
    const float* x1 = (const float*)d_in[1];
    const float* x2 = (const float*)d_in[2];
    const float* W0 = (const float*)d_in[3];
    const float* b0 = (const float*)d_in[4];
    const float* W1 = (const float*)d_in[5];
    const float* b1 = (const float*)d_in[6];
    const float* W2 = (const float*)d_in[7];
    const float* b2 = (const float*)d_in[8];
    float* out = (float*)d_out;

    prep_W<<<(56 * 96 * 32 + 255) / 256, 256>>>(W0, W1, W2);
    detect_tc<<<64 + 208 + 800, TPB>>>(x0, x1, x2, b0, b1, b2, out);
}

// round 8
// speedup vs baseline: 12.2701x; 1.0896x over previous
#include <cuda_runtime.h>
#include <cuda_fp16.h>
#include <cstdint>

// ============================================================
// Detect head via mma.sync, fp16 operands / fp32 accum.
// R8: double-buffered smem (X+W), one barrier per K chunk,
// ldmatrix.x4 for B fragments, hoisted swizzle addressing.
// ============================================================

#define TPB 256
#define SROW 88

#define XS0 0            // 32 k-rows x 256B (swizzled fp16)
#define XS1 8192
#define WS0 16384        // 96 n-rows x 80B
#define WS1 24064
#define SMEM_BYTES 31744 // epilogue S union: 64*88*4 = 22528

__device__ __forceinline__ uint32_t smem_u32(const void* p) {
    uint32_t a;
    asm("{ .reg .u64 t; cvta.to.shared.u64 t, %1; cvt.u32.u64 %0, t; }" : "=r"(a) : "l"(p));
    return a;
}

#define LDMX4T(r, addr) \
    asm volatile("ldmatrix.sync.aligned.m8n8.x4.trans.shared.b16 {%0,%1,%2,%3}, [%4];" \
        : "=r"((r)[0]), "=r"((r)[1]), "=r"((r)[2]), "=r"((r)[3]) : "r"(addr))

#define LDMX4(r, addr) \
    asm volatile("ldmatrix.sync.aligned.m8n8.x4.shared.b16 {%0,%1,%2,%3}, [%4];" \
        : "=r"((r)[0]), "=r"((r)[1]), "=r"((r)[2]), "=r"((r)[3]) : "r"(addr))

#define MMA16816(d, a, b0, b1) \
    asm volatile("mma.sync.aligned.m16n8k16.row.col.f32.f16.f16.f32 " \
        "{%0,%1,%2,%3}, {%4,%5,%6,%7}, {%8,%9}, {%0,%1,%2,%3};" \
        : "+f"((d)[0]), "+f"((d)[1]), "+f"((d)[2]), "+f"((d)[3]) \
        : "r"((a)[0]), "r"((a)[1]), "r"((a)[2]), "r"((a)[3]), "r"(b0), "r"(b1))

#define CP_ASYNC16(dst, src) \
    asm volatile("cp.async.ca.shared.global [%0], [%1], 16;" :: "r"(dst), "l"(src))
#define CP_COMMIT() asm volatile("cp.async.commit_group;" ::: "memory")
#define CP_WAIT0()  asm volatile("cp.async.wait_group 0;" ::: "memory")

// 56 chunks of 32 channels: [96 n][32 k] fp16 each
__device__ __align__(16) __half g_Wh[56 * 96 * 32];

__global__ void prep_W(const float* __restrict__ W0, const float* __restrict__ W1,
                       const float* __restrict__ W2)
{
    int idx = blockIdx.x * blockDim.x + threadIdx.x;
    if (idx >= 56 * 96 * 32) return;
    int ch = idx / 3072, rem = idx - ch * 3072;
    int n = rem >> 5, k = rem & 31;
    const float* W; int C, cb;
    if (ch < 8)       { W = W0; C = 256;  cb = ch * 32; }
    else if (ch < 24) { W = W1; C = 512;  cb = (ch - 8) * 32; }
    else              { W = W2; C = 1024; cb = (ch - 24) * 32; }
    float v = (n < 85) ? W[(size_t)n * C + cb + k] : 0.0f;
    g_Wh[idx] = __float2half(v);
}

__device__ __forceinline__ uint32_t h2u(__half2 h) {
    return *reinterpret_cast<uint32_t*>(&h);
}

template <int C, int NHW, int NX, int LEVEL>
__device__ __forceinline__
void run_level(const float* __restrict__ X, const float* __restrict__ bias,
               float* __restrict__ out, int lvlOff, int chBase, int b, int m0,
               char* sm, uint32_t sb)
{
    const int tid = threadIdx.x;
    const int lane = tid & 31, wid = tid >> 5;
    const int wm = wid >> 1, wn = wid & 1;
    constexpr int NCH = C / 32;
    const bool fullTile = (m0 + 128 <= NHW);
    const float* Xb = X + (size_t)b * C * NHW;

    float acc[2][6][4];
#pragma unroll
    for (int mf = 0; mf < 2; mf++)
#pragma unroll
        for (int f = 0; f < 6; f++)
#pragma unroll
            for (int e = 0; e < 4; e++) acc[mf][f][e] = 0.0f;

    // ---- hoisted addresses ----
    // X staging: this thread's 4 swizzled STS offsets + gmem pointers
    uint32_t offX[4];
    const float* px[4];
#pragma unroll
    for (int it = 0; it < 4; it++) {
        int idx = tid + it * TPB;
        int k = idx >> 5, m4 = idx & 31;
        offX[it] = (uint32_t)(k * 256 + ((m4 * 8) ^ ((k & 7) << 4)));
        px[it] = Xb + (size_t)k * NHW + m0 + m4 * 4;
    }
    // A ldmatrix: ks-invariant base offsets (k&7 == lane&7 for both ks)
    uint32_t aoffA[2];
    {
        const int mat = lane >> 3, r = lane & 7;
#pragma unroll
        for (int mf = 0; mf < 2; mf++) {
            int kb = ((mat >> 1) << 3) + r;
            int mb = (wm * 32 + mf * 16 + ((mat & 1) << 3)) * 2;
            aoffA[mf] = (uint32_t)(kb * 256 + (mb ^ (r << 4)));
        }
    }
    // B ldmatrix.x4: 3 per ks, each covers 2 f-tiles
    uint32_t relB[3];
    {
        const int grp = lane >> 3, rsel = lane & 7;
#pragma unroll
        for (int j = 0; j < 3; j++)
            relB[j] = (uint32_t)((wn * 48 + (j * 2 + (grp >> 1)) * 8 + rsel) * 80
                                 + (grp & 1) * 16);
    }
    // W cp.async dst offsets (relative to WS buffer base)
    uint32_t wrel0, wrel1 = 0;
    {
        int n = tid >> 2, k16 = tid & 3;
        wrel0 = (uint32_t)(n * 80 + k16 * 16);
        if (tid < 128) {
            int idx = tid + 256;
            wrel1 = (uint32_t)((idx >> 2) * 80 + (idx & 3) * 16);
        }
    }

    // X register-prefetch loader
    auto loadX = [&](int chk) {
        float4 v[4];
        if (fullTile) {
#pragma unroll
            for (int it = 0; it < 4; it++) {
                v[it] = *reinterpret_cast<const float4*>(px[it]);
                px[it] += 32 * NHW;
            }
        } else {
            int lim = NHW - 1 - m0;
#pragma unroll
            for (int it = 0; it < 4; it++) {
                int idx = tid + it * TPB;
                int k = chk * 32 + (idx >> 5), m4 = idx & 31;
                const float* src = Xb + (size_t)k * NHW + m0;
                v[it].x = src[min(m4 * 4 + 0, lim)];
                v[it].y = src[min(m4 * 4 + 1, lim)];
                v[it].z = src[min(m4 * 4 + 2, lim)];
                v[it].w = src[min(m4 * 4 + 3, lim)];
            }
        }
        return *reinterpret_cast<float4(*)[4]>(&v);
    };

    auto convertX = [&](const float4 (&v)[4], uint32_t xsOff) {
#pragma unroll
        for (int it = 0; it < 4; it++) {
            __half2 h0 = __floats2half2_rn(v[it].x, v[it].y);
            __half2 h1 = __floats2half2_rn(v[it].z, v[it].w);
            *reinterpret_cast<uint2*>(sm + xsOff + offX[it]) = make_uint2(h2u(h0), h2u(h1));
        }
    };

    auto stageW = [&](int chk, uint32_t wsOff) {
        const uint4* wsrc = reinterpret_cast<const uint4*>(
            &g_Wh[(size_t)(chBase + chk) * 3072]);
        CP_ASYNC16(sb + wsOff + wrel0, wsrc + tid);
        if (tid < 128) CP_ASYNC16(sb + wsOff + wrel1, wsrc + tid + 256);
        CP_COMMIT();
    };

    // ---- prologue: stage chunk 0, prefetch chunk 1 ----
    float4 v[4];
    {
        auto t = loadX(0);
#pragma unroll
        for (int it = 0; it < 4; it++) v[it] = t[it];
    }
    stageW(0, WS0);
    convertX(v, XS0);
    {
        auto t = loadX(1);
#pragma unroll
        for (int it = 0; it < 4; it++) v[it] = t[it];
    }
    CP_WAIT0();
    __syncthreads();

    for (int chk = 0; chk < NCH; chk++) {
        const uint32_t xsCur = (chk & 1) ? XS1 : XS0;
        const uint32_t wsCur = (chk & 1) ? WS1 : WS0;

        // ---- stage chunk+1 into the other buffer ----
        if (chk + 1 < NCH) {
            stageW(chk + 1, (chk & 1) ? WS0 : WS1);
            convertX(v, (chk & 1) ? XS0 : XS1);
            if (chk + 2 < NCH) {
                auto t = loadX(chk + 2);
#pragma unroll
                for (int it = 0; it < 4; it++) v[it] = t[it];
            }
        }

        // ---- MMA on current buffers ----
        const uint32_t xbase = sb + xsCur;
        const uint32_t wbase = sb + wsCur;
#pragma unroll
        for (int ks = 0; ks < 2; ks++) {
            uint32_t af[2][4];
            LDMX4T(af[0], xbase + aoffA[0] + ks * 4096);
            LDMX4T(af[1], xbase + aoffA[1] + ks * 4096);
#pragma unroll
            for (int j = 0; j < 3; j++) {
                uint32_t br[4];
                LDMX4(br, wbase + relB[j] + ks * 32);
                MMA16816(acc[0][2 * j + 0], af[0], br[0], br[1]);
                MMA16816(acc[1][2 * j + 0], af[1], br[0], br[1]);
                MMA16816(acc[0][2 * j + 1], af[0], br[2], br[3]);
                MMA16816(acc[1][2 * j + 1], af[1], br[2], br[3]);
            }
        }

        CP_WAIT0();
        __syncthreads();
    }

    // ---- bias + sigmoid ----
    const int g = lane >> 2, c0 = lane & 3;
#pragma unroll
    for (int f = 0; f < 6; f++) {
        int nb = wn * 48 + f * 8 + c0 * 2;
        float bv0 = (nb < 85) ? __ldg(&bias[nb]) : 0.0f;
        float bv1 = (nb + 1 < 85) ? __ldg(&bias[nb + 1]) : 0.0f;
#pragma unroll
        for (int mf = 0; mf < 2; mf++)
#pragma unroll
            for (int h = 0; h < 2; h++) {
                float p0 = acc[mf][f][h * 2 + 0] + bv0;
                float p1 = acc[mf][f][h * 2 + 1] + bv1;
                acc[mf][f][h * 2 + 0] = __fdividef(1.0f, 1.0f + __expf(-p0));
                acc[mf][f][h * 2 + 1] = __fdividef(1.0f, 1.0f + __expf(-p1));
            }
    }

    // ---- box decode (channels 0..3 live in wn==0, f==0, c0<2) ----
    if (wn == 0) {
        const float power = (float)(1 << LEVEL);
        const float strd  = (float)(8 << LEVEL);
#pragma unroll
        for (int mf = 0; mf < 2; mf++)
#pragma unroll
            for (int h = 0; h < 2; h++) {
                float s0 = acc[mf][0][h * 2 + 0];
                float s1 = acc[mf][0][h * 2 + 1];
                float q0 = 4.0f * s0 * s0 * power;
                float q1 = 4.0f * s1 * s1 * power;
                float p0 = __shfl_xor_sync(0xffffffffu, q0, 1);
                float p1 = __shfl_xor_sync(0xffffffffu, q1, 1);
                float dx1 = (c0 == 0) ? q0 : p0;
                float dy1 = (c0 == 0) ? q1 : p1;
                float dx2 = (c0 == 0) ? p0 : q0;
                float dy2 = (c0 == 0) ? p1 : q1;
                int pos = m0 + wm * 32 + mf * 16 + h * 8 + g;
                int iy = pos / NX, ix = pos - iy * NX;
                float x1 = ((float)ix + 1.0f - dx1) * strd;
                float y1 = ((float)iy + 1.0f - dy1) * strd;
                float x2 = ((float)ix + dx2) * strd;
                float y2 = ((float)iy + dy2) * strd;
                if (c0 == 0) {
                    acc[mf][0][h * 2 + 0] = 0.5f * (x1 + x2);
                    acc[mf][0][h * 2 + 1] = 0.5f * (y1 + y2);
                } else if (c0 == 1) {
                    acc[mf][0][h * 2 + 0] = x2 - x1;
                    acc[mf][0][h * 2 + 1] = y2 - y1;
                }
            }
    }

    // ---- staged coalesced store: 2 waves of 64 positions ----
    float* S = reinterpret_cast<float*>(sm);
#pragma unroll
    for (int w = 0; w < 2; w++) {
        __syncthreads();
        if ((wm >> 1) == w) {
            int mbase = (wm & 1) * 32;
#pragma unroll
            for (int mf = 0; mf < 2; mf++)
#pragma unroll
                for (int h = 0; h < 2; h++) {
                    int mrow = mbase + mf * 16 + h * 8 + g;
#pragma unroll
                    for (int f = 0; f < 6; f++) {
                        int n = wn * 48 + f * 8 + c0 * 2;
                        if (n + 1 < 85)
                            *reinterpret_cast<float2*>(&S[mrow * SROW + n]) =
                                make_float2(acc[mf][f][h * 2], acc[mf][f][h * 2 + 1]);
                        else if (n < 85)
                            S[mrow * SROW + n] = acc[mf][f][h * 2];
                    }
                }
        }
        __syncthreads();
        int valid = NHW - (m0 + w * 64);
        valid = valid < 0 ? 0 : (valid > 64 ? 64 : valid);
        int total = valid * 85;
        float* ob = out + ((size_t)b * 8400 + lvlOff + m0 + w * 64) * 85;
        for (int i = tid; i < total; i += TPB) {
            int p = i / 85, o = i - p * 85;
            ob[i] = S[p * SROW + o];
        }
    }
}

// grid order: L2 (longest, 32 chunks) first, then L1, then L0
__global__ __launch_bounds__(TPB, 2)
void detect_tc(const float* __restrict__ x0, const float* __restrict__ x1,
               const float* __restrict__ x2,
               const float* __restrict__ b0, const float* __restrict__ b1,
               const float* __restrict__ b2, float* __restrict__ out)
{
    __shared__ __align__(1024) char sm[SMEM_BYTES];
    uint32_t sb = smem_u32(sm);
    int bid = blockIdx.x;
    if (bid < 64) {                      // L2: 4 tiles x 16 batch
        int b = bid >> 2, t = bid & 3;
        run_level<1024, 400, 20, 2>(x2, b2, out, 8000, 24, b, t * 128, sm, sb);
    } else if (bid < 272) {              // L1: 13 tiles x 16 batch
        int q = bid - 64;
        int b = q / 13, t = q - b * 13;
        run_level<512, 1600, 40, 1>(x1, b1, out, 6400, 8, b, t * 128, sm, sb);
    } else {                             // L0: 50 tiles x 16 batch
        int q = bid - 272;
        int b = q / 50, t = q - b * 50;
        run_level<256, 6400, 80, 0>(x0, b0, out, 0, 0, b, t * 128, sm, sb);
    }
}

extern "C" void kernel_launch(void* const* d_in, const int* in_sizes, int n_in,
                              void* d_out, int out_size)
{
    const float* x0 = (const float*)d_in[0];
    const float* x1 = (const float*)d_in[1];
    const float* x2 = (const float*)d_in[2];
    const float* W0 = (const float*)d_in[3];
    const float* b0 = (const float*)d_in[4];
    const float* W1 = (const float*)d_in[5];
    const float* b1 = (const float*)d_in[6];
    const float* W2 = (const float*)d_in[7];
    const float* b2 = (const float*)d_in[8];
    float* out = (float*)d_out;

    prep_W<<<(56 * 96 * 32 + 255) / 256, 256>>>(W0, W1, W2);
    detect_tc<<<64 + 208 + 800, TPB>>>(x0, x1, x2, b0, b1, b2, out);
}